// round 2
// baseline (speedup 1.0000x reference)
#include <cuda_runtime.h>
#include <cuda_bf16.h>
#include <math.h>

// Problem constants
#define NROWS 512          // 256 pairs * 2 spectra
#define NPEAK 512          // peaks per spectrum
#define GROUPS 3333
#define BOUT 9999          // 3333 * 3
#define H0 1000
#define H1 800
#define H2 800
#define HE 400
#define C0_CHUNKS 80

// -------------------- scratch (device globals; no allocation) --------------------
// Per-peak entry: (a0,a1,a2, colbase-as-int). colbase = 3*g, or -1 for invalid.
__device__ float4 g_entries[NROWS * NPEAK];                // 4 MB
__device__ float  g_c0_part[C0_CHUNKS * H0];               // 320 KB
__device__ float  g_c0[H0];
__device__ float  g_h0[NROWS * H0];
__device__ float  g_h1[NROWS * H1];
__device__ float  g_h2[NROWS * H2];
__device__ float  g_emb[NROWS * HE];

// -------------------- K1: build compact per-peak entries --------------------
__global__ void __launch_bounds__(512) k_build(
    const float* __restrict__ mz, const float* __restrict__ inten,
    const float* __restrict__ binner_w)
{
    int row = blockIdx.x;
    int p   = threadIdx.x;
    int idx = row * NPEAK + p;
    float m  = mz[idx];
    float it = inten[idx];
    // reference: idx = int32((mz - 0)/0.01), mask = 0<=mz<1000, bins >= 99990 dropped
    float fb = __fdiv_rn(m, 0.01f);
    int b = (int)fb;
    float4 e;
    if (m >= 0.0f && m < 1000.0f && b >= 0 && b < GROUPS * 30) {
        int g = b / 30;
        int i = b - g * 30;
        float v = sqrtf(it);              // inten ** 0.5
        const float* bw = binner_w + (g * 30 + i) * 3;
        e = make_float4(v * bw[0], v * bw[1], v * bw[2], __int_as_float(3 * g));
    } else {
        e = make_float4(0.f, 0.f, 0.f, __int_as_float(-1));
    }
    g_entries[idx] = e;
}

// -------------------- K2a: c0 partials = (binner_b_flat @ w0), split-K --------------------
__global__ void __launch_bounds__(256) k_c0_part(
    const float* __restrict__ bbf, const float* __restrict__ w0)
{
    int c = blockIdx.x;
    int k0 = c * 125;
    int k1 = min(k0 + 125, BOUT);
    int t = threadIdx.x;
    if (t >= 250) return;
    float4 acc = make_float4(0.f, 0.f, 0.f, 0.f);
    for (int k = k0; k < k1; k++) {
        float b = bbf[k];
        float4 w = *((const float4*)(w0 + k * H0) + t);
        acc.x += b * w.x; acc.y += b * w.y; acc.z += b * w.z; acc.w += b * w.w;
    }
    *((float4*)(g_c0_part + c * H0) + t) = acc;
}

// -------------------- K2b: c0 = b0 + sum(partials), fixed order --------------------
__global__ void __launch_bounds__(256) k_c0_reduce(const float* __restrict__ b0)
{
    int j = blockIdx.x * 256 + threadIdx.x;
    if (j >= H0) return;
    float s = b0[j];
    #pragma unroll 4
    for (int c = 0; c < C0_CHUNKS; c++) s += g_c0_part[c * H0 + j];
    g_c0[j] = s;
}

// -------------------- K3: layer 0 sparse: h0 = relu(xs @ w0 + c0) --------------------
__global__ void __launch_bounds__(256) k_layer0(const float* __restrict__ w0)
{
    __shared__ float4 se[NPEAK];
    int row = blockIdx.x;
    const float4* ent = g_entries + row * NPEAK;
    for (int i = threadIdx.x; i < NPEAK; i += 256) se[i] = ent[i];
    __syncthreads();

    int t = threadIdx.x;
    if (t >= 250) return;
    float4 acc = *((const float4*)g_c0 + t);

    for (int e = 0; e < NPEAK; e++) {
        float4 E = se[e];
        int cb = __float_as_int(E.w);
        if (cb < 0) continue;   // uniform across block (same row)
        float4 a = *((const float4*)(w0 + (cb    ) * H0) + t);
        float4 b = *((const float4*)(w0 + (cb + 1) * H0) + t);
        float4 c = *((const float4*)(w0 + (cb + 2) * H0) + t);
        acc.x += E.x * a.x + E.y * b.x + E.z * c.x;
        acc.y += E.x * a.y + E.y * b.y + E.z * c.y;
        acc.z += E.x * a.z + E.y * b.z + E.z * c.z;
        acc.w += E.x * a.w + E.y * b.w + E.z * c.w;
    }
    acc.x = fmaxf(acc.x, 0.f);
    acc.y = fmaxf(acc.y, 0.f);
    acc.z = fmaxf(acc.z, 0.f);
    acc.w = fmaxf(acc.w, 0.f);
    *((float4*)(g_h0 + row * H0) + t) = acc;
}

// -------------------- K4: generic tiled SGEMM: C = act(A@W + bias) --------------------
// A: [M,K] row-major, W: [K,N] row-major. BM=BN=64, BK=8, 256 threads, 4x4 per thread.
// M divisible by 64, K divisible by 8 (always true here); N guarded.
__global__ void __launch_bounds__(256) k_sgemm(
    const float* __restrict__ A, const float* __restrict__ W,
    const float* __restrict__ bias, float* __restrict__ C,
    int M, int K, int N, int relu)
{
    __shared__ float As[8][68];
    __shared__ float Ws[8][68];
    int t = threadIdx.x;
    int m0 = blockIdx.y * 64;
    int n0 = blockIdx.x * 64;
    int tx = t & 15, ty = t >> 4;

    int am = t >> 2;          // 0..63
    int ak = (t & 3) * 2;     // 0,2,4,6
    int wk = t >> 5;          // 0..7
    int wn = (t & 31) * 2;    // 0..62

    float acc[4][4];
    #pragma unroll
    for (int i = 0; i < 4; i++)
        #pragma unroll
        for (int j = 0; j < 4; j++) acc[i][j] = 0.f;

    for (int k0 = 0; k0 < K; k0 += 8) {
        float2 av = *(const float2*)(A + (m0 + am) * K + k0 + ak);
        As[ak][am] = av.x;
        As[ak + 1][am] = av.y;

        float2 wv = make_float2(0.f, 0.f);
        if (n0 + wn < N) wv = *(const float2*)(W + (k0 + wk) * N + n0 + wn);
        Ws[wk][wn] = wv.x;
        Ws[wk][wn + 1] = wv.y;
        __syncthreads();

        #pragma unroll
        for (int kk = 0; kk < 8; kk++) {
            float4 a = *(const float4*)&As[kk][ty * 4];
            float4 b = *(const float4*)&Ws[kk][tx * 4];
            float ar[4] = {a.x, a.y, a.z, a.w};
            float br[4] = {b.x, b.y, b.z, b.w};
            #pragma unroll
            for (int i = 0; i < 4; i++)
                #pragma unroll
                for (int j = 0; j < 4; j++)
                    acc[i][j] += ar[i] * br[j];
        }
        __syncthreads();
    }

    #pragma unroll
    for (int i = 0; i < 4; i++) {
        int r = m0 + ty * 4 + i;
        #pragma unroll
        for (int j = 0; j < 4; j++) {
            int col = n0 + tx * 4 + j;
            if (col < N) {
                float v = acc[i][j] + bias[col];
                if (relu) v = fmaxf(v, 0.f);
                C[r * N + col] = v;
            }
        }
    }
}

// -------------------- K5: pairwise cosine similarity --------------------
__global__ void __launch_bounds__(128) k_cosine(float* __restrict__ out)
{
    int b = blockIdx.x;
    const float* e1 = g_emb + (2 * b) * HE;
    const float* e2 = e1 + HE;
    int t = threadIdx.x;
    float d = 0.f, s1 = 0.f, s2 = 0.f;
    for (int j = t; j < HE; j += 128) {
        float x = e1[j], y = e2[j];
        d += x * y; s1 += x * x; s2 += y * y;
    }
    #pragma unroll
    for (int o = 16; o > 0; o >>= 1) {
        d  += __shfl_down_sync(0xffffffffu, d, o);
        s1 += __shfl_down_sync(0xffffffffu, s1, o);
        s2 += __shfl_down_sync(0xffffffffu, s2, o);
    }
    __shared__ float sd[4], sa[4], sb[4];
    int w = t >> 5;
    if ((t & 31) == 0) { sd[w] = d; sa[w] = s1; sb[w] = s2; }
    __syncthreads();
    if (t == 0) {
        d  = sd[0] + sd[1] + sd[2] + sd[3];
        s1 = sa[0] + sa[1] + sa[2] + sa[3];
        s2 = sb[0] + sb[1] + sb[2] + sb[3];
        float n1 = fmaxf(sqrtf(s1), 1e-6f);
        float n2 = fmaxf(sqrtf(s2), 1e-6f);
        out[b] = d / (n1 * n2);
    }
}

// -------------------- launch --------------------
extern "C" void kernel_launch(void* const* d_in, const int* in_sizes, int n_in,
                              void* d_out, int out_size)
{
    const float* mz       = (const float*)d_in[0];
    const float* inten    = (const float*)d_in[1];
    const float* binner_w = (const float*)d_in[2];
    const float* binner_b = (const float*)d_in[3];   // flat (3333*3) == column order of x
    const float* w0       = (const float*)d_in[4];
    const float* b0       = (const float*)d_in[5];
    const float* w1       = (const float*)d_in[6];
    const float* b1       = (const float*)d_in[7];
    const float* w2       = (const float*)d_in[8];
    const float* b2       = (const float*)d_in[9];
    const float* we       = (const float*)d_in[10];
    const float* be       = (const float*)d_in[11];
    float* out = (float*)d_out;

    k_build<<<NROWS, NPEAK>>>(mz, inten, binner_w);
    k_c0_part<<<C0_CHUNKS, 256>>>(binner_b, w0);
    k_c0_reduce<<<4, 256>>>(b0);
    k_layer0<<<NROWS, 256>>>(w0);

    // h1 = relu(h0 @ w1 + b1)  [512,1000]x[1000,800]
    {
        float *A, *B, *Cc;
        cudaGetSymbolAddress((void**)&A, g_h0);
        cudaGetSymbolAddress((void**)&B, g_h1);
        dim3 grid((H1 + 63) / 64, NROWS / 64);
        k_sgemm<<<grid, 256>>>(A, w1, b1, B, NROWS, H0, H1, 1);
        // h2 = relu(h1 @ w2 + b2) [512,800]x[800,800]
        cudaGetSymbolAddress((void**)&Cc, g_h2);
        dim3 grid2((H2 + 63) / 64, NROWS / 64);
        k_sgemm<<<grid2, 256>>>(B, w2, b2, Cc, NROWS, H1, H2, 1);
        // emb = h2 @ we + be [512,800]x[800,400]
        float* E;
        cudaGetSymbolAddress((void**)&E, g_emb);
        dim3 grid3((HE + 63) / 64, NROWS / 64);
        k_sgemm<<<grid3, 256>>>(Cc, we, be, E, NROWS, H2, HE, 0);
    }

    k_cosine<<<256, 128>>>(out);
    (void)in_sizes; (void)n_in; (void)out_size;
}